// round 1
// baseline (speedup 1.0000x reference)
#include <cuda_runtime.h>

#define SIZE   128
#define STRIDE 129           // +1 padding: conflict-free for row AND column access
#define NSWEEP 30
#define EPSF   1e-6f

// Precomputed Thomas factors per sweep:
//   g_fwd[s][i] = ( -a_i (=+coeff_i),  1/dn_i )
//   g_ncs[s][i] = -c_star_i
__device__ float2 g_fwd[NSWEEP][SIZE];
__device__ float  g_ncs[NSWEEP][SIZE];

// ---------------------------------------------------------------------------
// Setup: one thread per sweep computes the tridiagonal factorization.
// Sweep s = 3*k + phase:
//   phase 0: X, t = k*DT,        dt = DT/2
//   phase 1: Y, t = k*DT + DT/2, dt = DT
//   phase 2: X, t = (k+1)*DT,    dt = DT/2
// ---------------------------------------------------------------------------
__global__ void setup_kernel(const float* __restrict__ abx, const float* __restrict__ atx,
                             const float* __restrict__ aqx, const float* __restrict__ bby,
                             const float* __restrict__ bty, const float* __restrict__ bqy)
{
    int s = threadIdx.x;
    if (s >= NSWEEP) return;
    int k = s / 3, phase = s - 3 * k;

    double td; float dt;
    const float *bp, *lp, *qp;
    if (phase == 0)      { td = k * 0.01;          dt = (float)(0.01 * 0.5); bp = abx; lp = atx; qp = aqx; }
    else if (phase == 1) { td = k * 0.01 + 0.005;  dt = 0.01f;               bp = bby; lp = bty; qp = bqy; }
    else                 { td = (k + 1) * 0.01;    dt = (float)(0.01 * 0.5); bp = abx; lp = atx; qp = aqx; }
    float t = (float)td;

    // v(i) = clip(base + lin*t + quad*t^2, EPS)
    auto vf = [&](int i) {
        float v = bp[i] + lp[i] * t + qp[i] * (t * t);
        return fmaxf(v, EPSF);
    };

    // streaming smooth3 (edge-padded) + Thomas forward factorization
    float vm = vf(0);
    float vc = vm;
    float vn = vf(1);

    // i = 0
    float coeff = (vm + vc + vn) * (1.0f / 3.0f) * dt;   // dh^2 = 1
    float b0    = 1.0f + coeff;                           // b[0] = 1 + coeff[0]
    float dn    = b0 + EPSF;                              // denom0
    float inv   = 1.0f / dn;
    float cs    = (-coeff) * inv;                         // c_star[0]
    g_fwd[s][0] = make_float2(coeff, inv);
    g_ncs[s][0] = -cs;
    float cs_prev = cs;
    vm = vc; vc = vn;

    for (int i = 1; i < SIZE; i++) {
        vn    = (i < SIZE - 1) ? vf(i + 1) : vc;          // edge pad
        coeff = (vm + vc + vn) * (1.0f / 3.0f) * dt;
        float bi = (i == SIZE - 1) ? (1.0f + coeff) : (1.0f + 2.0f * coeff);
        float ai = -coeff;
        dn  = bi - ai * cs_prev + EPSF;
        inv = 1.0f / dn;
        cs  = (-coeff) * inv;
        g_fwd[s][i] = make_float2(coeff, inv);
        g_ncs[s][i] = -cs;
        cs_prev = cs;
        vm = vc; vc = vn;
    }
}

// ---------------------------------------------------------------------------
// Main: one CTA per batch image. All 30 sweeps executed on a resident SMEM
// tile. Thread tid owns row tid (X sweeps) or column tid (Y sweeps).
// Forward-elimination intermediates ds[] live in registers (full unroll).
// ---------------------------------------------------------------------------
__global__ void __launch_bounds__(128, 3)
diffuse_kernel(const float* __restrict__ uin, float* __restrict__ uout)
{
    extern __shared__ float smem[];
    float*  tile = smem;                                   // SIZE*STRIDE floats
    float2* cfwd = (float2*)(smem + SIZE * STRIDE);        // byte offset 66048 (8B aligned)
    float*  ncs  = (float*)(cfwd + SIZE);

    const int    tid    = threadIdx.x;
    const size_t imgoff = (size_t)blockIdx.x * (SIZE * SIZE);
    const float* src    = uin + imgoff;
    float*       dst    = uout + imgoff;

    // Load image into padded SMEM tile (coalesced LDG, conflict-free STS)
    #pragma unroll 1
    for (int i = tid; i < SIZE * SIZE; i += 128) {
        tile[(i >> 7) * STRIDE + (i & 127)] = src[i];
    }

    #pragma unroll 1
    for (int s = 0; s < NSWEEP; s++) {
        __syncthreads();                  // previous sweep fully written
        cfwd[tid] = g_fwd[s][tid];        // stage this sweep's factors
        ncs[tid]  = g_ncs[s][tid];
        __syncthreads();

        const bool isY  = (s - (s / 3) * 3) == 1;
        const int  base = isY ? tid : tid * STRIDE;
        const int  stp  = isY ? STRIDE : 1;

        // Forward elimination: ds_i = (d_i + na_i*ds_{i-1}) * inv_i
        float ds[SIZE];
        float2 f    = cfwd[0];
        float dprev = tile[base] * f.y;
        ds[0] = dprev;
        #pragma unroll
        for (int i = 1; i < SIZE; i++) {
            f     = cfwd[i];
            dprev = fmaf(f.x, dprev, tile[base + i * stp]) * f.y;
            ds[i] = dprev;
        }

        // Back substitution: x_i = ds_i + ncs_i * x_{i+1}
        float x = dprev;                  // x[127] = ds[127]
        tile[base + (SIZE - 1) * stp] = x;
        #pragma unroll
        for (int i = SIZE - 2; i >= 0; i--) {
            x = fmaf(ncs[i], x, ds[i]);
            tile[base + i * stp] = x;
        }
    }

    __syncthreads();
    // Store result (conflict-free LDS, coalesced STG)
    #pragma unroll 1
    for (int i = tid; i < SIZE * SIZE; i += 128) {
        dst[i] = tile[(i >> 7) * STRIDE + (i & 127)];
    }
}

// ---------------------------------------------------------------------------
// Launch contract
// Inputs (metadata order):
//   0:u  1:alpha_base_x  2:alpha_base_y  3:beta_base_x  4:beta_base_y
//   5:alpha_time_coeff_x 6:alpha_time_coeff_y 7:beta_time_coeff_x 8:beta_time_coeff_y
//   9:alpha_time_quad_x 10:alpha_time_quad_y 11:beta_time_quad_x 12:beta_time_quad_y
// Reference uses: alpha_*_x for X sweeps, beta_*_y for Y sweeps.
// ---------------------------------------------------------------------------
extern "C" void kernel_launch(void* const* d_in, const int* in_sizes, int n_in,
                              void* d_out, int out_size)
{
    const float* u   = (const float*)d_in[0];
    const float* abx = (const float*)d_in[1];
    const float* bby = (const float*)d_in[4];
    const float* atx = (const float*)d_in[5];
    const float* bty = (const float*)d_in[8];
    const float* aqx = (const float*)d_in[9];
    const float* bqy = (const float*)d_in[12];
    float* out = (float*)d_out;

    const int smem_bytes = (SIZE * STRIDE + 2 * SIZE + SIZE) * (int)sizeof(float); // 67584
    cudaFuncSetAttribute(diffuse_kernel,
                         cudaFuncAttributeMaxDynamicSharedMemorySize, smem_bytes);

    const int batch = out_size / (SIZE * SIZE);  // 2048

    setup_kernel<<<1, 32>>>(abx, atx, aqx, bby, bty, bqy);
    diffuse_kernel<<<batch, 128, smem_bytes>>>(u, out);
}

// round 3
// speedup vs baseline: 1.8538x; 1.8538x over previous
#include <cuda_runtime.h>
#include <cuda_bf16.h>
#include <cstdint>

#define SIZE   128
#define NSWEEP 30
#define EPSF   1e-6f
#define PB     136                      // bf16 row pitch (elements): 272B = 17 x 16B units
#define OPHALF (SIZE * PB * 2)          // one 128xPB bf16 matrix = 34816 B
#define OPPAIR (2 * OPHALF)             // hi+lo pair = 69632 B

// ---------------------------------------------------------------------------
// Globals
// ---------------------------------------------------------------------------
__device__ float2 g_fwd[NSWEEP][SIZE];   // (coeff_i, 1/dn_i) per sweep
__device__ float  g_ncs[NSWEEP][SIZE];   // -c_star_i per sweep
// [ L_hi | L_lo | W_hi | W_lo ], each 128 x PB bf16 row-major
__device__ __align__(16) unsigned char g_ops[2 * OPPAIR];

// ---------------------------------------------------------------------------
// Helpers
// ---------------------------------------------------------------------------
__device__ __forceinline__ uint32_t smem_u32(const void* p) {
    uint32_t a;
    asm("{ .reg .u64 t; cvta.to.shared.u64 t, %1; cvt.u32.u64 %0, t; }" : "=r"(a) : "l"(p));
    return a;
}
__device__ __forceinline__ void ldm_x4(uint32_t* r, uint32_t addr) {
    asm volatile("ldmatrix.sync.aligned.m8n8.x4.shared.b16 {%0,%1,%2,%3}, [%4];"
                 : "=r"(r[0]), "=r"(r[1]), "=r"(r[2]), "=r"(r[3]) : "r"(addr));
}
__device__ __forceinline__ void ldm_x4t(uint32_t* r, uint32_t addr) {
    asm volatile("ldmatrix.sync.aligned.m8n8.x4.trans.shared.b16 {%0,%1,%2,%3}, [%4];"
                 : "=r"(r[0]), "=r"(r[1]), "=r"(r[2]), "=r"(r[3]) : "r"(addr));
}
__device__ __forceinline__ void mma16816(float* c, const uint32_t* a, const uint32_t* b) {
    asm volatile("mma.sync.aligned.m16n8k16.row.col.f32.bf16.bf16.f32 "
                 "{%0,%1,%2,%3}, {%4,%5,%6,%7}, {%8,%9}, {%0,%1,%2,%3};"
                 : "+f"(c[0]), "+f"(c[1]), "+f"(c[2]), "+f"(c[3])
                 : "r"(a[0]), "r"(a[1]), "r"(a[2]), "r"(a[3]), "r"(b[0]), "r"(b[1]));
}
__device__ __forceinline__ uint32_t pack_hi(float a, float b) {
    __nv_bfloat16 ha = __float2bfloat16(a), hb = __float2bfloat16(b);
    return (uint32_t)*(uint16_t*)&ha | ((uint32_t)*(uint16_t*)&hb << 16);
}
__device__ __forceinline__ uint32_t pack_lo(float a, float b) {
    __nv_bfloat16 ha = __float2bfloat16(a), hb = __float2bfloat16(b);
    float ra = a - __bfloat162float(ha), rb = b - __bfloat162float(hb);
    __nv_bfloat16 la = __float2bfloat16(ra), lb = __float2bfloat16(rb);
    return (uint32_t)*(uint16_t*)&la | ((uint32_t)*(uint16_t*)&lb << 16);
}

// ---------------------------------------------------------------------------
// setup1: per-sweep Thomas factorization (validated round 1)
// ---------------------------------------------------------------------------
__global__ void setup_kernel(const float* __restrict__ abx, const float* __restrict__ atx,
                             const float* __restrict__ aqx, const float* __restrict__ bby,
                             const float* __restrict__ bty, const float* __restrict__ bqy)
{
    int s = threadIdx.x;
    if (s >= NSWEEP) return;
    int k = s / 3, phase = s - 3 * k;

    double td; float dt;
    const float *bp, *lp, *qp;
    if (phase == 0)      { td = k * 0.01;         dt = 0.005f; bp = abx; lp = atx; qp = aqx; }
    else if (phase == 1) { td = k * 0.01 + 0.005; dt = 0.01f;  bp = bby; lp = bty; qp = bqy; }
    else                 { td = (k + 1) * 0.01;   dt = 0.005f; bp = abx; lp = atx; qp = aqx; }
    float t = (float)td;

    auto vf = [&](int i) {
        float v = bp[i] + lp[i] * t + qp[i] * (t * t);
        return fmaxf(v, EPSF);
    };

    float vm = vf(0), vc = vm, vn = vf(1);
    float coeff = (vm + vc + vn) * (1.0f / 3.0f) * dt;
    float dn  = (1.0f + coeff) + EPSF;
    float inv = 1.0f / dn;
    float cs  = (-coeff) * inv;
    g_fwd[s][0] = make_float2(coeff, inv);
    g_ncs[s][0] = -cs;
    float cs_prev = cs;
    vm = vc; vc = vn;

    for (int i = 1; i < SIZE; i++) {
        vn    = (i < SIZE - 1) ? vf(i + 1) : vc;
        coeff = (vm + vc + vn) * (1.0f / 3.0f) * dt;
        float bi = (i == SIZE - 1) ? (1.0f + coeff) : (1.0f + 2.0f * coeff);
        dn  = bi - (-coeff) * cs_prev + EPSF;
        inv = 1.0f / dn;
        cs  = (-coeff) * inv;
        g_fwd[s][i] = make_float2(coeff, inv);
        g_ncs[s][i] = -cs;
        cs_prev = cs;
        vm = vc; vc = vn;
    }
}

// ---------------------------------------------------------------------------
// setup2: build dense L (CTA1, Y sweeps / column solves) and W (CTA0, X sweeps
// / row solves) by applying sweeps to the identity, then split to bf16 hi/lo
// row-major (pitch PB) in g_ops.  out = L * u * W.
// ---------------------------------------------------------------------------
__device__ void solve_vec(float* tile, int base, int stp, const float2* fwd, const float* ncs) {
    float ds[SIZE];
    float2 f = fwd[0];
    float dp = tile[base] * f.y;
    ds[0] = dp;
    #pragma unroll
    for (int i = 1; i < SIZE; i++) {
        f  = fwd[i];
        dp = fmaf(f.x, dp, tile[base + i * stp]) * f.y;
        ds[i] = dp;
    }
    float x = dp;
    tile[base + (SIZE - 1) * stp] = x;
    #pragma unroll
    for (int i = SIZE - 2; i >= 0; i--) {
        x = fmaf(ncs[i], x, ds[i]);
        tile[base + i * stp] = x;
    }
}

__global__ void __launch_bounds__(128, 1) setup2_kernel()
{
    extern __shared__ float tile[];   // 128 x 129 fp32
    const int tid = threadIdx.x;
    const bool isL = (blockIdx.x == 1);

    for (int i = tid; i < SIZE * SIZE; i += 128) {
        int r = i >> 7, c = i & 127;
        tile[r * 129 + c] = (r == c) ? 1.0f : 0.0f;
    }
    __syncthreads();

    for (int s = 0; s < NSWEEP; s++) {
        int ph = s % 3;
        bool take = isL ? (ph == 1) : (ph != 1);
        if (!take) continue;
        int base = isL ? tid : tid * 129;
        int stp  = isL ? 129 : 1;
        solve_vec(tile, base, stp, g_fwd[s], g_ncs[s]);
    }
    __syncthreads();

    // Store row-major hi/lo: L at offset 0, W at offset OPPAIR.
    unsigned char* hi = g_ops + (isL ? 0 : OPPAIR);
    unsigned char* lo = hi + OPHALF;
    const int row = tid;
    for (int c = 0; c < SIZE; c += 2) {
        float a = tile[row * 129 + c], b = tile[row * 129 + c + 1];
        *(uint32_t*)(hi + (row * PB + c) * 2) = pack_hi(a, b);
        *(uint32_t*)(lo + (row * PB + c) * 2) = pack_lo(a, b);
    }
}

// ---------------------------------------------------------------------------
// Main kernel. SMEM: [BufU pair 69632 | BufOp pair 69632] = 139264 B.
// GEMM1: T = L(BufOp) * u(BufU);  GEMM2: out = T(BufU) * W(BufOp).
// ---------------------------------------------------------------------------
#define OFF_U  0u
#define OFF_OP 69632u
#define SMEM_TOTAL 139264u

// One warp computes a 32x64 tile of C = A*B (128^3, bf16 hi/lo 3-product split).
__device__ __forceinline__ void warp_gemm(uint32_t a_hi, uint32_t b_hi,
                                          int wm, int wn, int lane,
                                          float acc[2][8][4])
{
    const int lr = lane & 15;
    const int lc = (lane >> 4) << 3;

    #pragma unroll 1
    for (int kc = 0; kc < 8; kc++) {
        const int k0 = kc * 16;

        uint32_t ah[2][4], al[2][4];
        #pragma unroll
        for (int mi = 0; mi < 2; mi++) {
            uint32_t addr = a_hi + (uint32_t)(((32 * wm + 16 * mi + lr) * PB + k0 + lc) * 2);
            ldm_x4(ah[mi], addr);
            ldm_x4(al[mi], addr + OPHALF);
        }

        uint32_t bh[4][4], bl[4][4];
        #pragma unroll
        for (int nj2 = 0; nj2 < 4; nj2++) {
            uint32_t addr = b_hi + (uint32_t)(((k0 + lr) * PB + 64 * wn + 16 * nj2 + lc) * 2);
            ldm_x4t(bh[nj2], addr);
            ldm_x4t(bl[nj2], addr + OPHALF);
        }

        #pragma unroll
        for (int mi = 0; mi < 2; mi++) {
            #pragma unroll
            for (int nj = 0; nj < 8; nj++) {
                const uint32_t* bhp = &bh[nj >> 1][(nj & 1) * 2];
                const uint32_t* blp = &bl[nj >> 1][(nj & 1) * 2];
                mma16816(acc[mi][nj], ah[mi], bhp);   // hi*hi
                mma16816(acc[mi][nj], ah[mi], blp);   // hi*lo
                mma16816(acc[mi][nj], al[mi], bhp);   // lo*hi
            }
        }
    }
}

__global__ void __launch_bounds__(256, 1)
gemm_kernel(const float* __restrict__ uin, float* __restrict__ uout)
{
    extern __shared__ unsigned char smem[];
    const uint32_t sb = smem_u32(smem);

    const int tid = threadIdx.x, wid = tid >> 5, lane = tid & 31;
    const int wm = wid >> 1, wn = wid & 1;       // 4x2 warp grid over 128x128

    const size_t imgoff = (size_t)blockIdx.x * (SIZE * SIZE);
    const uint4* src4 = (const uint4*)(uin + imgoff);

    // ---- Phase A: load u, split to bf16 hi/lo row-major in BufU; copy L ----
    #pragma unroll 1
    for (int i = tid; i < SIZE * SIZE / 4; i += 256) {
        uint4 v = src4[i];
        float f0 = __uint_as_float(v.x), f1 = __uint_as_float(v.y);
        float f2 = __uint_as_float(v.z), f3 = __uint_as_float(v.w);
        int r = i >> 5, c = (i & 31) * 4;
        uint32_t eo = (uint32_t)((r * PB + c) * 2);
        *(uint2*)(smem + OFF_U + eo)          = make_uint2(pack_hi(f0, f1), pack_hi(f2, f3));
        *(uint2*)(smem + OFF_U + OPHALF + eo) = make_uint2(pack_lo(f0, f1), pack_lo(f2, f3));
    }
    {
        const uint4* s = (const uint4*)(g_ops);               // L pair
        uint4* d = (uint4*)(smem + OFF_OP);
        #pragma unroll 1
        for (int i = tid; i < OPPAIR / 16; i += 256) d[i] = s[i];
    }
    __syncthreads();

    // ---- GEMM1: T = L * u ----
    float acc[2][8][4];
    #pragma unroll
    for (int mi = 0; mi < 2; mi++)
        #pragma unroll
        for (int nj = 0; nj < 8; nj++)
            #pragma unroll
            for (int q = 0; q < 4; q++) acc[mi][nj][q] = 0.0f;

    warp_gemm(sb + OFF_OP, sb + OFF_U, wm, wn, lane, acc);
    __syncthreads();   // all warps done reading u and L

    // ---- Phase B: split T accumulators into BufU; copy W into BufOp ----
    {
        const int r0 = 32 * wm + (lane >> 2);
        const int c0 = 64 * wn + (lane & 3) * 2;
        #pragma unroll
        for (int mi = 0; mi < 2; mi++) {
            #pragma unroll
            for (int nj = 0; nj < 8; nj++) {
                float a0 = acc[mi][nj][0], a1 = acc[mi][nj][1];
                float a2 = acc[mi][nj][2], a3 = acc[mi][nj][3];
                int r = r0 + 16 * mi, c = c0 + 8 * nj;
                uint32_t e0 = (uint32_t)((r * PB + c) * 2);
                uint32_t e1 = (uint32_t)(((r + 8) * PB + c) * 2);
                *(uint32_t*)(smem + OFF_U + e0)          = pack_hi(a0, a1);
                *(uint32_t*)(smem + OFF_U + OPHALF + e0) = pack_lo(a0, a1);
                *(uint32_t*)(smem + OFF_U + e1)          = pack_hi(a2, a3);
                *(uint32_t*)(smem + OFF_U + OPHALF + e1) = pack_lo(a2, a3);
            }
        }
    }
    {
        const uint4* s = (const uint4*)(g_ops + OPPAIR);      // W pair
        uint4* d = (uint4*)(smem + OFF_OP);
        #pragma unroll 1
        for (int i = tid; i < OPPAIR / 16; i += 256) d[i] = s[i];
    }
    __syncthreads();

    // ---- GEMM2: out = T * W ----
    #pragma unroll
    for (int mi = 0; mi < 2; mi++)
        #pragma unroll
        for (int nj = 0; nj < 8; nj++)
            #pragma unroll
            for (int q = 0; q < 4; q++) acc[mi][nj][q] = 0.0f;

    warp_gemm(sb + OFF_U, sb + OFF_OP, wm, wn, lane, acc);

    // ---- Phase C: store fp32 accumulators directly to gmem ----
    float* dst = uout + imgoff;
    {
        const int r0 = 32 * wm + (lane >> 2);
        const int c0 = 64 * wn + (lane & 3) * 2;
        #pragma unroll
        for (int mi = 0; mi < 2; mi++) {
            #pragma unroll
            for (int nj = 0; nj < 8; nj++) {
                int r = r0 + 16 * mi, c = c0 + 8 * nj;
                *(float2*)(dst + r * SIZE + c)       = make_float2(acc[mi][nj][0], acc[mi][nj][1]);
                *(float2*)(dst + (r + 8) * SIZE + c) = make_float2(acc[mi][nj][2], acc[mi][nj][3]);
            }
        }
    }
}

// ---------------------------------------------------------------------------
extern "C" void kernel_launch(void* const* d_in, const int* in_sizes, int n_in,
                              void* d_out, int out_size)
{
    const float* u   = (const float*)d_in[0];
    const float* abx = (const float*)d_in[1];
    const float* bby = (const float*)d_in[4];
    const float* atx = (const float*)d_in[5];
    const float* bty = (const float*)d_in[8];
    const float* aqx = (const float*)d_in[9];
    const float* bqy = (const float*)d_in[12];
    float* out = (float*)d_out;

    cudaFuncSetAttribute(setup2_kernel, cudaFuncAttributeMaxDynamicSharedMemorySize,
                         SIZE * 129 * (int)sizeof(float));
    cudaFuncSetAttribute(gemm_kernel, cudaFuncAttributeMaxDynamicSharedMemorySize,
                         (int)SMEM_TOTAL);

    const int batch = out_size / (SIZE * SIZE);   // 2048

    setup_kernel<<<1, 32>>>(abx, atx, aqx, bby, bty, bqy);
    setup2_kernel<<<2, 128, SIZE * 129 * sizeof(float)>>>();
    gemm_kernel<<<batch, 256, SMEM_TOTAL>>>(u, out);
}

// round 4
// speedup vs baseline: 3.8564x; 2.0802x over previous
#include <cuda_runtime.h>
#include <cstdint>

#define SIZE   128
#define NSWEEP 30
#define EPSF   1e-6f
#define BW     6            // half bandwidth of final operators
#define TAPS   13           // 2*BW+1
#define KB     12           // half band of 10-sweep partial operators (overkill-safe)
#define PA     132          // fp32 pitch for u buffer (16B-aligned rows)
#define PT     129          // pitch for Tt / Sout (lane-stride-1 banks)

// ---------------------------------------------------------------------------
// Globals
// ---------------------------------------------------------------------------
__device__ float2 g_fwd[NSWEEP][SIZE];   // (coeff_i, 1/dn_i)
__device__ float  g_ncs[NSWEEP][SIZE];   // -c_star_i
__device__ float  g_P1[SIZE*SIZE], g_P2[SIZE*SIZE];   // X half-products (W = P1*P2)
__device__ float  g_Q1[SIZE*SIZE], g_Q2[SIZE*SIZE];   // Y half-products (L = Q2*Q1)
__device__ float  g_Lb[SIZE*TAPS], g_Wb[SIZE*TAPS];   // band coefficients

// ---------------------------------------------------------------------------
// S1: coefficient table in parallel, then 30 short Thomas chains.
// Sweep s = 3k+phase: ph0: X t=k*DT dt=DT/2; ph1: Y t=k*DT+DT/2 dt=DT;
// ph2: X t=(k+1)*DT dt=DT/2.
// ---------------------------------------------------------------------------
__global__ void setup1_kernel(const float* __restrict__ abx, const float* __restrict__ atx,
                              const float* __restrict__ aqx, const float* __restrict__ bby,
                              const float* __restrict__ bty, const float* __restrict__ bqy)
{
    __shared__ float co[NSWEEP][SIZE];
    const int tid = threadIdx.x;

    for (int idx = tid; idx < NSWEEP * SIZE; idx += 128) {
        int s = idx >> 7, i = idx & 127;
        int k = s / 3, ph = s - 3 * k;
        float t, dt; const float *bp, *lp, *qp;
        if (ph == 0)      { t = k * 0.01f;           dt = 0.005f; bp = abx; lp = atx; qp = aqx; }
        else if (ph == 1) { t = k * 0.01f + 0.005f;  dt = 0.01f;  bp = bby; lp = bty; qp = bqy; }
        else              { t = (k + 1) * 0.01f;     dt = 0.005f; bp = abx; lp = atx; qp = aqx; }
        int im = max(i - 1, 0), ip = min(i + 1, 127);
        float vm = fmaxf(bp[im] + lp[im] * t + qp[im] * t * t, EPSF);
        float vc = fmaxf(bp[i]  + lp[i]  * t + qp[i]  * t * t, EPSF);
        float vp = fmaxf(bp[ip] + lp[ip] * t + qp[ip] * t * t, EPSF);
        co[s][i] = (vm + vc + vp) * (1.0f / 3.0f) * dt;
    }
    __syncthreads();

    if (tid < NSWEEP) {
        const int s = tid;
        float cs_prev = 0.0f;
        for (int i = 0; i < SIZE; i++) {
            float c  = co[s][i];
            float bi = (i == 0 || i == SIZE - 1) ? (1.0f + c) : (1.0f + 2.0f * c);
            float dn = bi + c * cs_prev + EPSF;   // b - a*cs_prev, a = -c
            float inv = 1.0f / dn;
            float cs  = -c * inv;
            g_fwd[s][i] = make_float2(c, inv);
            g_ncs[s][i] = -cs;
            cs_prev = cs;
        }
    }
}

// ---------------------------------------------------------------------------
// S2: 4 CTAs build the half-products by applying sweep subsets to identity.
// part0: X sweeps 0..9 -> P1; part1: X sweeps 10..19 -> P2
// part2: Y sweeps 0..4 -> Q1; part3: Y sweeps 5..9 -> Q2
// X solves rows (tile <- tile * R^T), Y solves columns (tile <- R * tile).
// ---------------------------------------------------------------------------
__device__ void solve_vec(float* tile, int base, int stp, const float2* fwd, const float* ncs) {
    float ds[SIZE];
    float2 f = fwd[0];
    float dp = tile[base] * f.y;
    ds[0] = dp;
    #pragma unroll
    for (int i = 1; i < SIZE; i++) {
        f  = fwd[i];
        dp = fmaf(f.x, dp, tile[base + i * stp]) * f.y;
        ds[i] = dp;
    }
    float x = dp;
    tile[base + (SIZE - 1) * stp] = x;
    #pragma unroll
    for (int i = SIZE - 2; i >= 0; i--) {
        x = fmaf(ncs[i], x, ds[i]);
        tile[base + i * stp] = x;
    }
}

__global__ void __launch_bounds__(128, 1) setup2_kernel()
{
    extern __shared__ float tile[];   // 128 x 129
    const int tid  = threadIdx.x;
    const int part = blockIdx.x;
    const bool isY = part >= 2;
    const int lo = (part == 0) ? 0 : (part == 1) ? 10 : (part == 2) ? 0 : 5;
    const int hi = lo + (isY ? 5 : 10);

    for (int i = tid; i < SIZE * SIZE; i += 128) {
        int r = i >> 7, c = i & 127;
        tile[r * 129 + c] = (r == c) ? 1.0f : 0.0f;
    }
    __syncthreads();

    int cnt = 0;
    for (int s = 0; s < NSWEEP; s++) {
        bool ys = (s % 3) == 1;
        if (ys != isY) continue;
        if (cnt >= lo && cnt < hi) {
            int base = isY ? tid : tid * 129;
            int stp  = isY ? 129 : 1;
            solve_vec(tile, base, stp, g_fwd[s], g_ncs[s]);
        }
        cnt++;
    }
    __syncthreads();

    float* dst = (part == 0) ? g_P1 : (part == 1) ? g_P2 : (part == 2) ? g_Q1 : g_Q2;
    for (int i = tid; i < SIZE * SIZE; i += 128)
        dst[i] = tile[(i >> 7) * 129 + (i & 127)];
}

// ---------------------------------------------------------------------------
// S3: banded recombination.  W = P1*P2, L = Q2*Q1; extract TAPS-wide bands.
//   Wb[j][d] = W[j-BW+d][j],  Lb[i][d] = L[i][i-BW+d]   (zero outside range)
// ---------------------------------------------------------------------------
__global__ void setup3_kernel()
{
    const int j = threadIdx.x;
    const int kmin = max(0, j - KB), kmax = min(127, j + KB);

    for (int d = 0; d < TAPS; d++) {
        int r = j - BW + d;
        float sum = 0.0f;
        if (r >= 0 && r < SIZE) {
            for (int k = kmin; k <= kmax; k++)
                sum += g_P1[r * SIZE + k] * g_P2[k * SIZE + j];
        }
        g_Wb[j * TAPS + d] = sum;
    }
    for (int d = 0; d < TAPS; d++) {
        int cc = j - BW + d;
        float sum = 0.0f;
        if (cc >= 0 && cc < SIZE) {
            for (int k = kmin; k <= kmax; k++)
                sum += g_Q2[j * SIZE + k] * g_Q1[k * SIZE + cc];
        }
        g_Lb[j * TAPS + d] = sum;
    }
}

// ---------------------------------------------------------------------------
// Main: one CTA per image, 256 threads (8 warps).
// Pass (generic, column-direction sliding window):
//   out[row i][col jq] = sum_t coeff[i][t] * src[i-BW+t][jq]
// warp w owns rows [16w, 16w+16); lane owns columns {lane, lane+32, +64, +96}.
// dst written TRANSPOSED at pitch PT (conflict-free: lane*PT % 32 == lane),
// which makes pass2 structurally identical to pass1 and the final store
// coalesced.
// ---------------------------------------------------------------------------
__device__ __noinline__ void band_pass(const float* __restrict__ src, int sp,
                                       const float* __restrict__ coeff,
                                       float* __restrict__ dst,
                                       int lane, int i0)
{
    float win[TAPS][4];
    #pragma unroll
    for (int t = 0; t < TAPS - 1; t++) {
        int r = i0 - BW + t; r = r < 0 ? 0 : r;          // clamped: coeff is 0 there
        #pragma unroll
        for (int q = 0; q < 4; q++) win[t][q] = src[r * sp + lane + 32 * q];
    }
    #pragma unroll
    for (int ii = 0; ii < 16; ii++) {
        const int i  = i0 + ii;
        int rn = i + BW; rn = rn > 127 ? 127 : rn;       // clamped: coeff is 0 there
        #pragma unroll
        for (int q = 0; q < 4; q++)
            win[(ii + TAPS - 1) % TAPS][q] = src[rn * sp + lane + 32 * q];

        float a0 = 0.f, a1 = 0.f, a2 = 0.f, a3 = 0.f;
        #pragma unroll
        for (int t = 0; t < TAPS; t++) {
            float c = coeff[i * TAPS + t];               // warp-uniform broadcast LDS
            a0 = fmaf(c, win[(ii + t) % TAPS][0], a0);
            a1 = fmaf(c, win[(ii + t) % TAPS][1], a1);
            a2 = fmaf(c, win[(ii + t) % TAPS][2], a2);
            a3 = fmaf(c, win[(ii + t) % TAPS][3], a3);
        }
        dst[(lane     ) * PT + i] = a0;
        dst[(lane + 32) * PT + i] = a1;
        dst[(lane + 64) * PT + i] = a2;
        dst[(lane + 96) * PT + i] = a3;
    }
}

__global__ void __launch_bounds__(256, 1)
band_kernel(const float* __restrict__ uin, float* __restrict__ uout)
{
    extern __shared__ float sm[];
    float* uA  = sm;                       // u (pitch PA); later Sout (pitch PT view)
    float* Tt  = sm + SIZE * PA;           // T transposed (pitch PT)
    float* LbS = Tt + SIZE * PT;
    float* WbS = LbS + SIZE * TAPS;

    const int tid  = threadIdx.x;
    const int w    = tid >> 5, lane = tid & 31;
    const size_t off = (size_t)blockIdx.x * (SIZE * SIZE);

    // Phase 0: coalesced vector load of u into pitch-PA tile (conflict-free STS.128)
    const float4* src4 = (const float4*)(uin + off);
    #pragma unroll 1
    for (int m = tid; m < SIZE * SIZE / 4; m += 256) {
        float4 v = src4[m];
        int r = m >> 5, c4 = (m & 31) * 4;
        *(float4*)&uA[r * PA + c4] = v;
    }
    #pragma unroll 1
    for (int m = tid; m < SIZE * TAPS; m += 256) { LbS[m] = g_Lb[m]; WbS[m] = g_Wb[m]; }
    __syncthreads();

    // Pass 1: Tt[j][i] = sum_t Lb[i][t] * u[i-BW+t][j]
    band_pass(uA, PA, LbS, Tt, lane, w * 16);
    __syncthreads();

    // Pass 2: Sout[i][j] = sum_t Wb[j][t] * Tt[j-BW+t][i]   (Sout = uA, pitch PT)
    band_pass(Tt, PT, WbS, uA, lane, w * 16);
    __syncthreads();

    // Phase 3: coalesced store (conflict-free LDS: consecutive lanes, +lane banks)
    float* dst = uout + off;
    #pragma unroll 1
    for (int m = tid; m < SIZE * SIZE; m += 256) {
        int r = m >> 7, c = m & 127;
        dst[m] = uA[r * PT + c];
    }
}

// ---------------------------------------------------------------------------
extern "C" void kernel_launch(void* const* d_in, const int* in_sizes, int n_in,
                              void* d_out, int out_size)
{
    const float* u   = (const float*)d_in[0];
    const float* abx = (const float*)d_in[1];
    const float* bby = (const float*)d_in[4];
    const float* atx = (const float*)d_in[5];
    const float* bty = (const float*)d_in[8];
    const float* aqx = (const float*)d_in[9];
    const float* bqy = (const float*)d_in[12];
    float* out = (float*)d_out;

    const int smem_s2 = SIZE * 129 * (int)sizeof(float);                    // 66048
    const int smem_m  = (SIZE * PA + SIZE * PT + 2 * SIZE * TAPS) * 4;      // 146944

    cudaFuncSetAttribute(setup2_kernel, cudaFuncAttributeMaxDynamicSharedMemorySize, smem_s2);
    cudaFuncSetAttribute(band_kernel,   cudaFuncAttributeMaxDynamicSharedMemorySize, smem_m);

    const int batch = out_size / (SIZE * SIZE);   // 2048

    setup1_kernel<<<1, 128>>>(abx, atx, aqx, bby, bty, bqy);
    setup2_kernel<<<4, 128, smem_s2>>>();
    setup3_kernel<<<1, 128>>>();
    band_kernel<<<batch, 256, smem_m>>>(u, out);
}

// round 5
// speedup vs baseline: 5.3548x; 1.3886x over previous
#include <cuda_runtime.h>
#include <cstdint>

#define SIZE   128
#define NSWEEP 30
#define EPSF   1e-6f
#define BW     6            // half bandwidth of final operators
#define TAPS   13           // 2*BW+1
#define KBC    10           // k-range half-width for 5-sweep chain products
#define KBE    12           // band half-width of 10-sweep partials E1,E2
#define PA     132          // fp32 pitch for u buffer
#define PT     129          // pitch for Tt / Sout

// ---------------------------------------------------------------------------
// Globals
// ---------------------------------------------------------------------------
__device__ float2 g_fwd[NSWEEP][SIZE];   // (coeff_i, 1/dn_i)
__device__ float  g_ncs[NSWEEP][SIZE];   // -c_star_i
// chains: 0..3 = X chains C1..C4 (W = C1*C2*C3*C4), 4 = Q1, 5 = Q2 (L = Q2*Q1)
__device__ float  g_chain[6][SIZE * SIZE];
__device__ float  g_Lb[SIZE * TAPS], g_Wb[SIZE * TAPS];

// ---------------------------------------------------------------------------
// S1: coefficient table in parallel, then 30 short Thomas chains.
// ---------------------------------------------------------------------------
__global__ void setup1_kernel(const float* __restrict__ abx, const float* __restrict__ atx,
                              const float* __restrict__ aqx, const float* __restrict__ bby,
                              const float* __restrict__ bty, const float* __restrict__ bqy)
{
    __shared__ float co[NSWEEP][SIZE];
    const int tid = threadIdx.x;

    for (int idx = tid; idx < NSWEEP * SIZE; idx += 128) {
        int s = idx >> 7, i = idx & 127;
        int k = s / 3, ph = s - 3 * k;
        float t, dt; const float *bp, *lp, *qp;
        if (ph == 0)      { t = k * 0.01f;           dt = 0.005f; bp = abx; lp = atx; qp = aqx; }
        else if (ph == 1) { t = k * 0.01f + 0.005f;  dt = 0.01f;  bp = bby; lp = bty; qp = bqy; }
        else              { t = (k + 1) * 0.01f;     dt = 0.005f; bp = abx; lp = atx; qp = aqx; }
        int im = max(i - 1, 0), ip = min(i + 1, 127);
        float vm = fmaxf(bp[im] + lp[im] * t + qp[im] * t * t, EPSF);
        float vc = fmaxf(bp[i]  + lp[i]  * t + qp[i]  * t * t, EPSF);
        float vp = fmaxf(bp[ip] + lp[ip] * t + qp[ip] * t * t, EPSF);
        co[s][i] = (vm + vc + vp) * (1.0f / 3.0f) * dt;
    }
    __syncthreads();

    if (tid < NSWEEP) {
        const int s = tid;
        float cs_prev = 0.0f;
        for (int i = 0; i < SIZE; i++) {
            float c  = co[s][i];
            float bi = (i == 0 || i == SIZE - 1) ? (1.0f + c) : (1.0f + 2.0f * c);
            float dn = bi + c * cs_prev + EPSF;
            float inv = 1.0f / dn;
            float cs  = -c * inv;
            g_fwd[s][i] = make_float2(c, inv);
            g_ncs[s][i] = -cs;
            cs_prev = cs;
        }
    }
}

// ---------------------------------------------------------------------------
// S2: 6 CTAs, each applies a 5-sweep chain to the identity.
// parts 0..3: X chains (row solves), sweep-in-direction index [5p, 5p+5)
// parts 4..5: Y chains (column solves), index [0,5) / [5,10)
// ---------------------------------------------------------------------------
__device__ void solve_vec(float* tile, int base, int stp, const float2* fwd, const float* ncs) {
    float ds[SIZE];
    float2 f = fwd[0];
    float dp = tile[base] * f.y;
    ds[0] = dp;
    #pragma unroll
    for (int i = 1; i < SIZE; i++) {
        f  = fwd[i];
        dp = fmaf(f.x, dp, tile[base + i * stp]) * f.y;
        ds[i] = dp;
    }
    float x = dp;
    tile[base + (SIZE - 1) * stp] = x;
    #pragma unroll
    for (int i = SIZE - 2; i >= 0; i--) {
        x = fmaf(ncs[i], x, ds[i]);
        tile[base + i * stp] = x;
    }
}

__global__ void __launch_bounds__(128, 1) setup2_kernel()
{
    extern __shared__ float tile[];   // 128 x 129
    const int tid  = threadIdx.x;
    const int part = blockIdx.x;
    const bool isY = part >= 4;
    const int lo = isY ? (part - 4) * 5 : part * 5;
    const int hi = lo + 5;

    for (int i = tid; i < SIZE * SIZE; i += 128) {
        int r = i >> 7, c = i & 127;
        tile[r * 129 + c] = (r == c) ? 1.0f : 0.0f;
    }
    __syncthreads();

    int cnt = 0;
    for (int s = 0; s < NSWEEP; s++) {
        bool ys = (s % 3) == 1;
        if (ys != isY) continue;
        if (cnt >= lo && cnt < hi) {
            int base = isY ? tid : tid * 129;
            int stp  = isY ? 129 : 1;
            solve_vec(tile, base, stp, g_fwd[s], g_ncs[s]);
        }
        cnt++;
    }
    __syncthreads();

    float* dst = g_chain[part];
    for (int i = tid; i < SIZE * SIZE; i += 128)
        dst[i] = tile[(i >> 7) * 129 + (i & 127)];
}

// ---------------------------------------------------------------------------
// S3: banded composition, single CTA of 1024 threads.
// Stage 1: E1 = C1*C2, E2 = C3*C4 (band KBE, smem); Lb = band(Q2*Q1).
// Stage 2: Wb = band(E1*E2).
// ---------------------------------------------------------------------------
__global__ void __launch_bounds__(1024, 1) setup3_kernel()
{
    extern __shared__ float es[];         // E1 | E2, each 128x128
    float* E1 = es;
    float* E2 = es + SIZE * SIZE;
    const int tid = threadIdx.x;

    for (int m = tid; m < 2 * SIZE * SIZE; m += 1024) es[m] = 0.0f;
    __syncthreads();

    // Stage 1a: E1, E2 band entries
    const int WE = 2 * KBE + 1;
    const int NE = SIZE * WE;
    for (int idx = tid; idx < 2 * NE; idx += 1024) {
        int e  = idx / NE;
        int m2 = idx - e * NE;
        int r  = m2 / WE;
        int k  = r - KBE + (m2 - r * WE);
        if (k < 0 || k > 127) continue;
        const float* A = g_chain[e * 2];       // C1 or C3
        const float* B = g_chain[e * 2 + 1];   // C2 or C4
        int mlo = max(max(r, k) - KBC, 0), mhi = min(min(r, k) + KBC, 127);
        float s = 0.0f;
        for (int m = mlo; m <= mhi; m++) s += A[r * SIZE + m] * B[m * SIZE + k];
        (e ? E2 : E1)[r * SIZE + k] = s;
    }

    // Stage 1b: Lb[i][d] = (Q2*Q1)[i][i-BW+d]
    for (int idx = tid; idx < SIZE * TAPS; idx += 1024) {
        int i = idx / TAPS, d = idx - i * TAPS;
        int cc = i - BW + d;
        float s = 0.0f;
        if (cc >= 0 && cc < SIZE) {
            int klo = max(max(i, cc) - KBC, 0), khi = min(min(i, cc) + KBC, 127);
            for (int k = klo; k <= khi; k++)
                s += g_chain[5][i * SIZE + k] * g_chain[4][k * SIZE + cc];
        }
        g_Lb[idx] = s;
    }
    __syncthreads();

    // Stage 2: Wb[j][d] = (E1*E2)[j-BW+d][j]
    for (int idx = tid; idx < SIZE * TAPS; idx += 1024) {
        int j = idx / TAPS, d = idx - j * TAPS;
        int r = j - BW + d;
        float s = 0.0f;
        if (r >= 0 && r < SIZE) {
            int klo = max(max(r, j) - KBE, 0), khi = min(min(r, j) + KBE, 127);
            for (int k = klo; k <= khi; k++)
                s += E1[r * SIZE + k] * E2[k * SIZE + j];
        }
        g_Wb[idx] = s;
    }
}

// ---------------------------------------------------------------------------
// Main: one CTA per image, 512 threads (16 warps, 8 rows per warp).
//   out[row i][col jq] = sum_t coeff[i][t] * src[i-BW+t][jq]
// lane owns columns {lane, lane+32, +64, +96}; dst written TRANSPOSED at
// pitch PT (conflict-free), so pass2 is structurally identical and the final
// store is coalesced.
// ---------------------------------------------------------------------------
__device__ __noinline__ void band_pass(const float* __restrict__ src, int sp,
                                       const float* __restrict__ coeff,
                                       float* __restrict__ dst,
                                       int lane, int i0)
{
    float win[TAPS][4];
    #pragma unroll
    for (int t = 0; t < TAPS - 1; t++) {
        int r = i0 - BW + t; r = r < 0 ? 0 : r;          // clamped: coeff is 0 there
        #pragma unroll
        for (int q = 0; q < 4; q++) win[t][q] = src[r * sp + lane + 32 * q];
    }
    #pragma unroll
    for (int ii = 0; ii < 8; ii++) {
        const int i  = i0 + ii;
        int rn = i + BW; rn = rn > 127 ? 127 : rn;       // clamped: coeff is 0 there
        #pragma unroll
        for (int q = 0; q < 4; q++)
            win[(ii + TAPS - 1) % TAPS][q] = src[rn * sp + lane + 32 * q];

        float a0 = 0.f, a1 = 0.f, a2 = 0.f, a3 = 0.f;
        #pragma unroll
        for (int t = 0; t < TAPS; t++) {
            float c = coeff[i * TAPS + t];               // warp-uniform broadcast LDS
            a0 = fmaf(c, win[(ii + t) % TAPS][0], a0);
            a1 = fmaf(c, win[(ii + t) % TAPS][1], a1);
            a2 = fmaf(c, win[(ii + t) % TAPS][2], a2);
            a3 = fmaf(c, win[(ii + t) % TAPS][3], a3);
        }
        dst[(lane     ) * PT + i] = a0;
        dst[(lane + 32) * PT + i] = a1;
        dst[(lane + 64) * PT + i] = a2;
        dst[(lane + 96) * PT + i] = a3;
    }
}

__global__ void __launch_bounds__(512, 1)
band_kernel(const float* __restrict__ uin, float* __restrict__ uout)
{
    extern __shared__ float sm[];
    float* uA  = sm;                       // u (pitch PA); later Sout (pitch PT)
    float* Tt  = sm + SIZE * PA;           // T transposed (pitch PT)
    float* LbS = Tt + SIZE * PT;
    float* WbS = LbS + SIZE * TAPS;

    const int tid  = threadIdx.x;
    const int w    = tid >> 5, lane = tid & 31;
    const size_t off = (size_t)blockIdx.x * (SIZE * SIZE);

    // Phase 0: coalesced vector load of u into pitch-PA tile
    const float4* src4 = (const float4*)(uin + off);
    #pragma unroll 1
    for (int m = tid; m < SIZE * SIZE / 4; m += 512) {
        float4 v = src4[m];
        int r = m >> 5, c4 = (m & 31) * 4;
        *(float4*)&uA[r * PA + c4] = v;
    }
    #pragma unroll 1
    for (int m = tid; m < SIZE * TAPS; m += 512) { LbS[m] = g_Lb[m]; WbS[m] = g_Wb[m]; }
    __syncthreads();

    // Pass 1: Tt[j][i] = sum_t Lb[i][t] * u[i-BW+t][j]
    band_pass(uA, PA, LbS, Tt, lane, w * 8);
    __syncthreads();

    // Pass 2: Sout[i][j] = sum_t Wb[j][t] * Tt[j-BW+t][i]
    band_pass(Tt, PT, WbS, uA, lane, w * 8);
    __syncthreads();

    // Phase 3: coalesced store
    float* dst = uout + off;
    #pragma unroll 1
    for (int m = tid; m < SIZE * SIZE; m += 512) {
        int r = m >> 7, c = m & 127;
        dst[m] = uA[r * PT + c];
    }
}

// ---------------------------------------------------------------------------
extern "C" void kernel_launch(void* const* d_in, const int* in_sizes, int n_in,
                              void* d_out, int out_size)
{
    const float* u   = (const float*)d_in[0];
    const float* abx = (const float*)d_in[1];
    const float* bby = (const float*)d_in[4];
    const float* atx = (const float*)d_in[5];
    const float* bty = (const float*)d_in[8];
    const float* aqx = (const float*)d_in[9];
    const float* bqy = (const float*)d_in[12];
    float* out = (float*)d_out;

    const int smem_s2 = SIZE * 129 * (int)sizeof(float);                 // 66048
    const int smem_s3 = 2 * SIZE * SIZE * (int)sizeof(float);            // 131072
    const int smem_m  = (SIZE * PA + SIZE * PT + 2 * SIZE * TAPS) * 4;   // 146944

    cudaFuncSetAttribute(setup2_kernel, cudaFuncAttributeMaxDynamicSharedMemorySize, smem_s2);
    cudaFuncSetAttribute(setup3_kernel, cudaFuncAttributeMaxDynamicSharedMemorySize, smem_s3);
    cudaFuncSetAttribute(band_kernel,   cudaFuncAttributeMaxDynamicSharedMemorySize, smem_m);

    const int batch = out_size / (SIZE * SIZE);   // 2048

    setup1_kernel<<<1, 128>>>(abx, atx, aqx, bby, bty, bqy);
    setup2_kernel<<<6, 128, smem_s2>>>();
    setup3_kernel<<<1, 1024, smem_s3>>>();
    band_kernel<<<batch, 512, smem_m>>>(u, out);
}

// round 6
// speedup vs baseline: 6.1753x; 1.1532x over previous
#include <cuda_runtime.h>
#include <cstdint>

#define SIZE   128
#define NSWEEP 30
#define EPSF   1e-6f
#define BW     4            // half bandwidth of final operators
#define TAPS   9            // 2*BW+1
#define CW     12           // padded coeff row width (float4-friendly)
#define KBC    10           // chain band half-width (5-sweep products)
#define CBW    21           // chain band storage width
#define KBE    12           // E (10-sweep) band half-width
#define EW     25           // E band storage width
#define PA     132          // fp32 pitch for uA staging

// ---------------------------------------------------------------------------
// Globals
// ---------------------------------------------------------------------------
__device__ float2 g_fwd[NSWEEP][SIZE];       // (coeff_i, 1/dn_i)
__device__ float  g_ncs[NSWEEP][SIZE];       // -c_star_i
// banded chains: 0..3 = X chains C1..C4 (W = C1*C2*C3*C4), 4 = Q1, 5 = Q2 (L = Q2*Q1)
__device__ float  g_cb[6][SIZE * CBW];
__device__ float  g_Lb[SIZE * CW], g_Wb[SIZE * CW];   // padded band coefficients

// ---------------------------------------------------------------------------
// S1: coefficient table in parallel, then 30 short Thomas chains.
// ---------------------------------------------------------------------------
__global__ void setup1_kernel(const float* __restrict__ abx, const float* __restrict__ atx,
                              const float* __restrict__ aqx, const float* __restrict__ bby,
                              const float* __restrict__ bty, const float* __restrict__ bqy)
{
    __shared__ float co[NSWEEP][SIZE];
    const int tid = threadIdx.x;

    for (int idx = tid; idx < NSWEEP * SIZE; idx += 128) {
        int s = idx >> 7, i = idx & 127;
        int k = s / 3, ph = s - 3 * k;
        float t, dt; const float *bp, *lp, *qp;
        if (ph == 0)      { t = k * 0.01f;           dt = 0.005f; bp = abx; lp = atx; qp = aqx; }
        else if (ph == 1) { t = k * 0.01f + 0.005f;  dt = 0.01f;  bp = bby; lp = bty; qp = bqy; }
        else              { t = (k + 1) * 0.01f;     dt = 0.005f; bp = abx; lp = atx; qp = aqx; }
        int im = max(i - 1, 0), ip = min(i + 1, 127);
        float vm = fmaxf(bp[im] + lp[im] * t + qp[im] * t * t, EPSF);
        float vc = fmaxf(bp[i]  + lp[i]  * t + qp[i]  * t * t, EPSF);
        float vp = fmaxf(bp[ip] + lp[ip] * t + qp[ip] * t * t, EPSF);
        co[s][i] = (vm + vc + vp) * (1.0f / 3.0f) * dt;
    }
    __syncthreads();

    if (tid < NSWEEP) {
        const int s = tid;
        float cs_prev = 0.0f;
        for (int i = 0; i < SIZE; i++) {
            float c  = co[s][i];
            float bi = (i == 0 || i == SIZE - 1) ? (1.0f + c) : (1.0f + 2.0f * c);
            float dn = bi + c * cs_prev + EPSF;
            float inv = 1.0f / dn;
            float cs  = -c * inv;
            g_fwd[s][i] = make_float2(c, inv);
            g_ncs[s][i] = -cs;
            cs_prev = cs;
        }
    }
}

// ---------------------------------------------------------------------------
// S2: 6 CTAs, each applies a 5-sweep chain to the identity, stores the BAND.
// parts 0..3: X chains (row solves), parts 4..5: Y chains (column solves).
// ---------------------------------------------------------------------------
__device__ void solve_vec(float* tile, int base, int stp, const float2* fwd, const float* ncs) {
    float ds[SIZE];
    float2 f = fwd[0];
    float dp = tile[base] * f.y;
    ds[0] = dp;
    #pragma unroll
    for (int i = 1; i < SIZE; i++) {
        f  = fwd[i];
        dp = fmaf(f.x, dp, tile[base + i * stp]) * f.y;
        ds[i] = dp;
    }
    float x = dp;
    tile[base + (SIZE - 1) * stp] = x;
    #pragma unroll
    for (int i = SIZE - 2; i >= 0; i--) {
        x = fmaf(ncs[i], x, ds[i]);
        tile[base + i * stp] = x;
    }
}

__global__ void __launch_bounds__(128, 1) setup2_kernel()
{
    extern __shared__ float tile[];   // 128 x 129
    const int tid  = threadIdx.x;
    const int part = blockIdx.x;
    const bool isY = part >= 4;
    const int lo = isY ? (part - 4) * 5 : part * 5;
    const int hi = lo + 5;

    for (int i = tid; i < SIZE * SIZE; i += 128) {
        int r = i >> 7, c = i & 127;
        tile[r * 129 + c] = (r == c) ? 1.0f : 0.0f;
    }
    __syncthreads();

    int cnt = 0;
    for (int s = 0; s < NSWEEP; s++) {
        bool ys = (s % 3) == 1;
        if (ys != isY) continue;
        if (cnt >= lo && cnt < hi) {
            int base = isY ? tid : tid * 129;
            int stp  = isY ? 129 : 1;
            solve_vec(tile, base, stp, g_fwd[s], g_ncs[s]);
        }
        cnt++;
    }
    __syncthreads();

    // band extract: Cb[r][d] = C[r][r-KBC+d]
    const int r = tid;
    for (int d = 0; d < CBW; d++) {
        int c = r - KBC + d;
        g_cb[part][r * CBW + d] = (c >= 0 && c < SIZE) ? tile[r * 129 + c] : 0.0f;
    }
}

// ---------------------------------------------------------------------------
// S3: all band-composition in one 1024-thread CTA, data in smem.
// E1 = C1*C2, E2 = C3*C4 (band KBE); Lb = band_BW(Q2*Q1); Wb = band_BW(E1*E2).
// ---------------------------------------------------------------------------
__global__ void __launch_bounds__(1024, 1) setup3_kernel()
{
    extern __shared__ float s3[];
    float* cb = s3;                      // 6*128*21 = 16128
    float* E  = s3 + 6 * SIZE * CBW;     // 2*128*25 = 6400
    const int tid = threadIdx.x;

    for (int m = tid; m < 6 * SIZE * CBW; m += 1024)
        cb[m] = ((const float*)g_cb)[m];
    __syncthreads();

    // E bands
    for (int idx = tid; idx < 2 * SIZE * EW; idx += 1024) {
        int e = idx / (SIZE * EW);
        int rem = idx - e * (SIZE * EW);
        int r = rem / EW, d = rem - r * EW;
        int c = r - KBE + d;
        float s = 0.0f;
        if (c >= 0 && c < SIZE) {
            const float* A = cb + (2 * e)     * SIZE * CBW;   // C1 / C3
            const float* B = cb + (2 * e + 1) * SIZE * CBW;   // C2 / C4
            int klo = max(max(r, c) - KBC, 0), khi = min(min(r, c) + KBC, 127);
            for (int k = klo; k <= khi; k++)
                s += A[r * CBW + (k - r + KBC)] * B[k * CBW + (c - k + KBC)];
        }
        E[idx] = s;
    }

    // Lb[i][d] = (Q2*Q1)[i][i-BW+d], padded to CW with zeros
    for (int idx = tid; idx < SIZE * CW; idx += 1024) {
        int i = idx / CW, d = idx - i * CW;
        float s = 0.0f;
        if (d < TAPS) {
            int c = i - BW + d;
            if (c >= 0 && c < SIZE) {
                const float* Q2 = cb + 5 * SIZE * CBW;
                const float* Q1 = cb + 4 * SIZE * CBW;
                int klo = max(max(i, c) - KBC, 0), khi = min(min(i, c) + KBC, 127);
                for (int k = klo; k <= khi; k++)
                    s += Q2[i * CBW + (k - i + KBC)] * Q1[k * CBW + (c - k + KBC)];
            }
        }
        g_Lb[idx] = s;
    }
    __syncthreads();

    // Wb[j][d] = (E1*E2)[j-BW+d][j], padded to CW
    for (int idx = tid; idx < SIZE * CW; idx += 1024) {
        int j = idx / CW, d = idx - j * CW;
        float s = 0.0f;
        if (d < TAPS) {
            int r = j - BW + d;
            if (r >= 0 && r < SIZE) {
                const float* E1 = E, *E2 = E + SIZE * EW;
                int mlo = max(max(r, j) - KBE, 0), mhi = min(min(r, j) + KBE, 127);
                for (int m = mlo; m <= mhi; m++)
                    s += E1[r * EW + (m - r + KBE)] * E2[m * EW + (j - m + KBE)];
            }
        }
        g_Wb[idx] = s;
    }
}

// ---------------------------------------------------------------------------
// Main: one CTA per image, 512 threads (16 warps, 8 rows per warp).
// Lane owns 4 CONSECUTIVE columns as float4. Transposed dst uses XOR swizzle
// col4 ^ ((row>>2)&7): conflict-free for both the STS.128 transposed stores
// (4 output rows batched, register-transposed) and the pass-2 LDS.128 reads.
// ---------------------------------------------------------------------------
__device__ __forceinline__ float4 f4fma(float c, float4 w, float4 a) {
    a.x = fmaf(c, w.x, a.x); a.y = fmaf(c, w.y, a.y);
    a.z = fmaf(c, w.z, a.z); a.w = fmaf(c, w.w, a.w);
    return a;
}

template<bool SWZ, int SP>
__device__ __forceinline__ float4 src_ld(const float* __restrict__ src, int r, int lane) {
    int col4  = SWZ ? (lane ^ ((r >> 2) & 7)) : lane;
    int pitch = SWZ ? SIZE : SP;
    return *(const float4*)&src[r * pitch + 4 * col4];
}

template<bool SWZ, int SP>
__device__ void band_pass(const float* __restrict__ src,
                          const float* __restrict__ coeff,
                          float* __restrict__ dst, int lane, int i0)
{
    float4 win[TAPS];
    #pragma unroll
    for (int t = 0; t < TAPS - 1; t++) {
        int r = i0 - BW + t; r = r < 0 ? 0 : r;      // clamped: coeff is 0 there
        win[t] = src_ld<SWZ, SP>(src, r, lane);
    }
    float4 acc[4];
    #pragma unroll
    for (int ii = 0; ii < 8; ii++) {
        const int i = i0 + ii;
        int rn = i + BW; rn = rn > 127 ? 127 : rn;   // clamped: coeff is 0 there
        win[(ii + TAPS - 1) % TAPS] = src_ld<SWZ, SP>(src, rn, lane);

        float4 c0 = *(const float4*)&coeff[i * CW];
        float4 c1 = *(const float4*)&coeff[i * CW + 4];
        float  c8 = coeff[i * CW + 8];
        float4 a = make_float4(0.f, 0.f, 0.f, 0.f);
        a = f4fma(c0.x, win[(ii + 0) % TAPS], a);
        a = f4fma(c0.y, win[(ii + 1) % TAPS], a);
        a = f4fma(c0.z, win[(ii + 2) % TAPS], a);
        a = f4fma(c0.w, win[(ii + 3) % TAPS], a);
        a = f4fma(c1.x, win[(ii + 4) % TAPS], a);
        a = f4fma(c1.y, win[(ii + 5) % TAPS], a);
        a = f4fma(c1.z, win[(ii + 6) % TAPS], a);
        a = f4fma(c1.w, win[(ii + 7) % TAPS], a);
        a = f4fma(c8,   win[(ii + 8) % TAPS], a);
        acc[ii & 3] = a;

        if ((ii & 3) == 3) {                          // i-3 is a multiple of 4
            const int sw = 4 * (((i - 3) >> 2) ^ (lane & 7));
            #pragma unroll
            for (int c = 0; c < 4; c++) {
                int j = 4 * lane + c;                 // (j>>2)&7 == lane&7
                float4 v = make_float4(((float*)&acc[0])[c], ((float*)&acc[1])[c],
                                       ((float*)&acc[2])[c], ((float*)&acc[3])[c]);
                *(float4*)&dst[j * SIZE + sw] = v;
            }
        }
    }
}

__global__ void __launch_bounds__(512, 1)
band_kernel(const float* __restrict__ uin, float* __restrict__ uout)
{
    extern __shared__ float sm[];
    float* uA  = sm;                        // 128*PA staging; reused as Sout (swizzled)
    float* Tt  = sm + SIZE * PA;            // 128*128 swizzled transposed intermediate
    float* LbS = Tt + SIZE * SIZE;          // 128*CW
    float* WbS = LbS + SIZE * CW;

    const int tid = threadIdx.x, w = tid >> 5, lane = tid & 31;
    const size_t off = (size_t)blockIdx.x * (SIZE * SIZE);

    // Phase 0: coalesced float4 load of u
    const float4* src4 = (const float4*)(uin + off);
    #pragma unroll 1
    for (int m = tid; m < SIZE * SIZE / 4; m += 512) {
        float4 v = src4[m];
        int r = m >> 5, c4 = (m & 31) * 4;
        *(float4*)&uA[r * PA + c4] = v;
    }
    #pragma unroll 1
    for (int m = tid; m < SIZE * CW; m += 512) { LbS[m] = g_Lb[m]; WbS[m] = g_Wb[m]; }
    __syncthreads();

    // Pass 1: Tt[j][i] = sum_t Lb[i][t] * u[i-BW+t][j]   (dst swizzled)
    band_pass<false, PA>(uA, LbS, Tt, lane, w * 8);
    __syncthreads();

    // Pass 2: Sout[r][j] = sum_t Wb[j][t] * T[r][j-BW+t]  (src+dst swizzled; dst = uA)
    band_pass<true, 0>(Tt, WbS, uA, lane, w * 8);
    __syncthreads();

    // Phase 3: coalesced float4 store
    float4* dst4 = (float4*)(uout + off);
    #pragma unroll 1
    for (int m = tid; m < SIZE * SIZE / 4; m += 512) {
        int r = m >> 5, mi = m & 31;
        dst4[m] = *(const float4*)&uA[r * SIZE + 4 * (mi ^ ((r >> 2) & 7))];
    }
}

// ---------------------------------------------------------------------------
extern "C" void kernel_launch(void* const* d_in, const int* in_sizes, int n_in,
                              void* d_out, int out_size)
{
    const float* u   = (const float*)d_in[0];
    const float* abx = (const float*)d_in[1];
    const float* bby = (const float*)d_in[4];
    const float* atx = (const float*)d_in[5];
    const float* bty = (const float*)d_in[8];
    const float* aqx = (const float*)d_in[9];
    const float* bqy = (const float*)d_in[12];
    float* out = (float*)d_out;

    const int smem_s2 = SIZE * 129 * (int)sizeof(float);                    // 66048
    const int smem_s3 = (6 * SIZE * CBW + 2 * SIZE * EW) * (int)sizeof(float); // 90112
    const int smem_m  = (SIZE * PA + SIZE * SIZE + 2 * SIZE * CW) * 4;      // 145408

    cudaFuncSetAttribute(setup2_kernel, cudaFuncAttributeMaxDynamicSharedMemorySize, smem_s2);
    cudaFuncSetAttribute(setup3_kernel, cudaFuncAttributeMaxDynamicSharedMemorySize, smem_s3);
    cudaFuncSetAttribute(band_kernel,   cudaFuncAttributeMaxDynamicSharedMemorySize, smem_m);

    const int batch = out_size / (SIZE * SIZE);   // 2048

    setup1_kernel<<<1, 128>>>(abx, atx, aqx, bby, bty, bqy);
    setup2_kernel<<<6, 128, smem_s2>>>();
    setup3_kernel<<<1, 1024, smem_s3>>>();
    band_kernel<<<batch, 512, smem_m>>>(u, out);
}

// round 7
// speedup vs baseline: 10.1803x; 1.6486x over previous
#include <cuda_runtime.h>
#include <cstdint>

#define SIZE   128
#define EPSF   1e-6f
#define BW     4            // half bandwidth of final operators
#define TAPS   9            // 2*BW+1
#define CW     12           // padded coeff row width
#define KBC    10           // chain band half-width (5-sweep products)
#define CBW    21           // chain band storage width
#define KBE    12           // E (10-sweep) band half-width
#define EW     25           // E band storage width
#define RSTRIP 64           // rows per band CTA
#define UROWS  (RSTRIP + 2 * BW)   // 72

// ---------------------------------------------------------------------------
// Globals
// ---------------------------------------------------------------------------
// banded chains: 0..3 = X chains C1..C4 (W = C1*C2*C3*C4), 4 = Q1, 5 = Q2 (L = Q2*Q1)
__device__ float g_cb[6][SIZE * CBW];
__device__ float g_Lb[SIZE * CW], g_Wb[SIZE * CW];   // padded band coefficients

// ---------------------------------------------------------------------------
// setup_ops: 6 CTAs. Each computes its 5 sweeps' coefficients (parallel),
// Thomas factors (5 lanes, rcp.approx breaks the div chain), applies the
// 5 solves to the identity, extracts the band.
// X chain part p covers X-order sweeps [5p,5p+5); m-th X sweep: k=m>>1,
// t=(k+(m&1))*DT, dt=DT/2. Y parts 4,5 cover Y-order [0,5),[5,10);
// m-th Y sweep: t=m*DT+DT/2, dt=DT.
// ---------------------------------------------------------------------------
__device__ void solve_vec(float* tile, int base, int stp,
                          const float* cf, const float* inv, const float* ncs) {
    float ds[SIZE];
    float dp = tile[base] * inv[0];
    ds[0] = dp;
    #pragma unroll
    for (int i = 1; i < SIZE; i++) {
        dp = fmaf(cf[i], dp, tile[base + i * stp]) * inv[i];
        ds[i] = dp;
    }
    float x = dp;
    tile[base + (SIZE - 1) * stp] = x;
    #pragma unroll
    for (int i = SIZE - 2; i >= 0; i--) {
        x = fmaf(ncs[i], x, ds[i]);
        tile[base + i * stp] = x;
    }
}

__global__ void __launch_bounds__(128, 1)
setup_ops_kernel(const float* __restrict__ abx, const float* __restrict__ atx,
                 const float* __restrict__ aqx, const float* __restrict__ bby,
                 const float* __restrict__ bty, const float* __restrict__ bqy)
{
    extern __shared__ float sh[];
    float* tile = sh;                        // 128*129
    float* co   = sh + SIZE * 129;           // 5*128 coeff rows (= fwd c)
    float* fI   = co + 5 * SIZE;             // 5*128 inv(dn)
    float* fN   = fI + 5 * SIZE;             // 5*128 -c_star

    const int tid  = threadIdx.x;
    const int part = blockIdx.x;
    const bool isY = part >= 4;

    // coefficient rows
    #pragma unroll 1
    for (int q = 0; q < 5; q++) {
        int m = isY ? (part - 4) * 5 + q : part * 5 + q;
        float t, dt; const float *bp, *lp, *qp;
        if (isY) { t = m * 0.01f + 0.005f;           dt = 0.01f;  bp = bby; lp = bty; qp = bqy; }
        else     { int k = m >> 1; t = (k + (m & 1)) * 0.01f; dt = 0.005f; bp = abx; lp = atx; qp = aqx; }
        int i = tid;
        int im = max(i - 1, 0), ip = min(i + 1, 127);
        float vm = fmaxf(bp[im] + lp[im] * t + qp[im] * t * t, EPSF);
        float vc = fmaxf(bp[i]  + lp[i]  * t + qp[i]  * t * t, EPSF);
        float vp = fmaxf(bp[ip] + lp[ip] * t + qp[ip] * t * t, EPSF);
        co[q * SIZE + i] = (vm + vc + vp) * (1.0f / 3.0f) * dt;
    }
    // identity tile
    for (int i = tid; i < SIZE * SIZE; i += 128)
        tile[(i >> 7) * 129 + (i & 127)] = ((i >> 7) == (i & 127)) ? 1.0f : 0.0f;
    __syncthreads();

    // Thomas factorization, one lane per sweep
    if (tid < 5) {
        const float* c = &co[tid * SIZE];
        float cs_prev = 0.0f;
        for (int i = 0; i < SIZE; i++) {
            float ci = c[i];
            float bi = (i == 0 || i == SIZE - 1) ? (1.0f + ci) : (1.0f + 2.0f * ci);
            float dn = bi + ci * cs_prev + EPSF;
            float inv;
            asm("rcp.approx.f32 %0, %1;" : "=f"(inv) : "f"(dn));
            float cs = -ci * inv;
            fI[tid * SIZE + i] = inv;
            fN[tid * SIZE + i] = -cs;
            cs_prev = cs;
        }
    }
    __syncthreads();

    const int base = isY ? tid : tid * 129;
    const int stp  = isY ? 129 : 1;
    #pragma unroll 1
    for (int q = 0; q < 5; q++)
        solve_vec(tile, base, stp, &co[q * SIZE], &fI[q * SIZE], &fN[q * SIZE]);
    __syncthreads();

    // band extract: Cb[r][d] = C[r][r-KBC+d]
    const int r = tid;
    for (int d = 0; d < CBW; d++) {
        int c = r - KBC + d;
        g_cb[part][r * CBW + d] = (c >= 0 && c < SIZE) ? tile[r * 129 + c] : 0.0f;
    }
}

// ---------------------------------------------------------------------------
// setup3: band composition in one 1024-thread CTA.
// E1 = C1*C2, E2 = C3*C4 (band KBE); Lb = band_BW(Q2*Q1); Wb = band_BW(E1*E2).
// ---------------------------------------------------------------------------
__global__ void __launch_bounds__(1024, 1) setup3_kernel()
{
    extern __shared__ float s3[];
    float* cb = s3;                      // 6*128*21
    float* E  = s3 + 6 * SIZE * CBW;     // 2*128*25
    const int tid = threadIdx.x;

    for (int m = tid; m < 6 * SIZE * CBW; m += 1024)
        cb[m] = ((const float*)g_cb)[m];
    __syncthreads();

    for (int idx = tid; idx < 2 * SIZE * EW; idx += 1024) {
        int e = idx / (SIZE * EW);
        int rem = idx - e * (SIZE * EW);
        int r = rem / EW, d = rem - r * EW;
        int c = r - KBE + d;
        float s = 0.0f;
        if (c >= 0 && c < SIZE) {
            const float* A = cb + (2 * e)     * SIZE * CBW;
            const float* B = cb + (2 * e + 1) * SIZE * CBW;
            int klo = max(max(r, c) - KBC, 0), khi = min(min(r, c) + KBC, 127);
            for (int k = klo; k <= khi; k++)
                s += A[r * CBW + (k - r + KBC)] * B[k * CBW + (c - k + KBC)];
        }
        E[idx] = s;
    }

    for (int idx = tid; idx < SIZE * CW; idx += 1024) {
        int i = idx / CW, d = idx - i * CW;
        float s = 0.0f;
        if (d < TAPS) {
            int c = i - BW + d;
            if (c >= 0 && c < SIZE) {
                const float* Q2 = cb + 5 * SIZE * CBW;
                const float* Q1 = cb + 4 * SIZE * CBW;
                int klo = max(max(i, c) - KBC, 0), khi = min(min(i, c) + KBC, 127);
                for (int k = klo; k <= khi; k++)
                    s += Q2[i * CBW + (k - i + KBC)] * Q1[k * CBW + (c - k + KBC)];
            }
        }
        g_Lb[idx] = s;
    }
    __syncthreads();

    for (int idx = tid; idx < SIZE * CW; idx += 1024) {
        int j = idx / CW, d = idx - j * CW;
        float s = 0.0f;
        if (d < TAPS) {
            int r = j - BW + d;
            if (r >= 0 && r < SIZE) {
                const float* E1 = E, *E2 = E + SIZE * EW;
                int mlo = max(max(r, j) - KBE, 0), mhi = min(min(r, j) + KBE, 127);
                for (int m = mlo; m <= mhi; m++)
                    s += E1[r * EW + (m - r + KBE)] * E2[m * EW + (j - m + KBE)];
            }
        }
        g_Wb[idx] = s;
    }
}

// ---------------------------------------------------------------------------
// band_kernel: 2 CTAs per image (64-row strips), 256 threads, 8 rows/warp.
// Per row: pass1 = 9 LDS.128 + 36 FMA -> T row (float4/lane);
// pass2 = 8 SHFL + 36 FMA with register-resident Wb; 1 coalesced STG.128.
// ---------------------------------------------------------------------------
__device__ __forceinline__ float4 f4fma(float c, float4 w, float4 a) {
    a.x = fmaf(c, w.x, a.x); a.y = fmaf(c, w.y, a.y);
    a.z = fmaf(c, w.z, a.z); a.w = fmaf(c, w.w, a.w);
    return a;
}

__global__ void __launch_bounds__(256, 3)
band_kernel(const float* __restrict__ uin, float* __restrict__ uout)
{
    extern __shared__ float sm[];
    float* us  = sm;                    // UROWS * 128
    float* Lbs = sm + UROWS * SIZE;     // RSTRIP * CW

    const int tid  = threadIdx.x, w = tid >> 5, lane = tid & 31;
    const int img  = blockIdx.x >> 1;
    const int r0   = (blockIdx.x & 1) * RSTRIP;
    const size_t off = (size_t)img * (SIZE * SIZE);
    const float* src = uin + off;

    // load u strip rows [r0-4, r0+68) clamped (halo rows have zero coeffs)
    #pragma unroll
    for (int q = 0; q < UROWS * SIZE / 4 / 256; q++) {   // 9 iters
        int m = tid + q * 256;
        int r = m >> 5, c4 = (m & 31) * 4;
        int gr = r0 - BW + r;
        gr = min(max(gr, 0), SIZE - 1);
        *(float4*)&us[r * SIZE + c4] = *(const float4*)&src[gr * SIZE + c4];
    }
    // Lb rows for this strip
    #pragma unroll 1
    for (int m = tid; m < RSTRIP * CW / 4; m += 256)
        ((float4*)Lbs)[m] = ((const float4*)&g_Lb[r0 * CW])[m];

    // per-lane Wb registers (columns 4*lane .. 4*lane+3)
    float wb[4][TAPS];
    #pragma unroll
    for (int c = 0; c < 4; c++) {
        const float* wr = &g_Wb[(4 * lane + c) * CW];
        float4 a0 = *(const float4*)wr;
        float4 a1 = *(const float4*)(wr + 4);
        wb[c][0] = a0.x; wb[c][1] = a0.y; wb[c][2] = a0.z; wb[c][3] = a0.w;
        wb[c][4] = a1.x; wb[c][5] = a1.y; wb[c][6] = a1.z; wb[c][7] = a1.w;
        wb[c][8] = wr[8];
    }
    __syncthreads();

    float* dst = uout + off;
    #pragma unroll
    for (int rr = 0; rr < 8; rr++) {
        const int il = w * 8 + rr;                 // local row; global i = r0 + il
        // ---- pass 1: T row ----
        const float* cr = &Lbs[il * CW];
        float4 c0 = *(const float4*)cr;
        float4 c1 = *(const float4*)(cr + 4);
        float  c8 = cr[8];
        const float* ub = &us[il * SIZE + 4 * lane];
        float4 t4 = make_float4(0.f, 0.f, 0.f, 0.f);
        t4 = f4fma(c0.x, *(const float4*)(ub + 0 * SIZE), t4);
        t4 = f4fma(c0.y, *(const float4*)(ub + 1 * SIZE), t4);
        t4 = f4fma(c0.z, *(const float4*)(ub + 2 * SIZE), t4);
        t4 = f4fma(c0.w, *(const float4*)(ub + 3 * SIZE), t4);
        t4 = f4fma(c1.x, *(const float4*)(ub + 4 * SIZE), t4);
        t4 = f4fma(c1.y, *(const float4*)(ub + 5 * SIZE), t4);
        t4 = f4fma(c1.z, *(const float4*)(ub + 6 * SIZE), t4);
        t4 = f4fma(c1.w, *(const float4*)(ub + 7 * SIZE), t4);
        t4 = f4fma(c8,   *(const float4*)(ub + 8 * SIZE), t4);

        // ---- pass 2: row stencil via shuffles (edge garbage hits zero coeffs) ----
        float Tl[12];
        Tl[0] = __shfl_up_sync(0xffffffffu, t4.x, 1);
        Tl[1] = __shfl_up_sync(0xffffffffu, t4.y, 1);
        Tl[2] = __shfl_up_sync(0xffffffffu, t4.z, 1);
        Tl[3] = __shfl_up_sync(0xffffffffu, t4.w, 1);
        Tl[4] = t4.x; Tl[5] = t4.y; Tl[6] = t4.z; Tl[7] = t4.w;
        Tl[8]  = __shfl_down_sync(0xffffffffu, t4.x, 1);
        Tl[9]  = __shfl_down_sync(0xffffffffu, t4.y, 1);
        Tl[10] = __shfl_down_sync(0xffffffffu, t4.z, 1);
        Tl[11] = __shfl_down_sync(0xffffffffu, t4.w, 1);

        float4 o = make_float4(0.f, 0.f, 0.f, 0.f);
        #pragma unroll
        for (int d = 0; d < TAPS; d++) {
            o.x = fmaf(wb[0][d], Tl[0 + d], o.x);
            o.y = fmaf(wb[1][d], Tl[1 + d], o.y);
            o.z = fmaf(wb[2][d], Tl[2 + d], o.z);
            o.w = fmaf(wb[3][d], Tl[3 + d], o.w);
        }
        *(float4*)&dst[(r0 + il) * SIZE + 4 * lane] = o;
    }
}

// ---------------------------------------------------------------------------
extern "C" void kernel_launch(void* const* d_in, const int* in_sizes, int n_in,
                              void* d_out, int out_size)
{
    const float* u   = (const float*)d_in[0];
    const float* abx = (const float*)d_in[1];
    const float* bby = (const float*)d_in[4];
    const float* atx = (const float*)d_in[5];
    const float* bty = (const float*)d_in[8];
    const float* aqx = (const float*)d_in[9];
    const float* bqy = (const float*)d_in[12];
    float* out = (float*)d_out;

    const int smem_so = (SIZE * 129 + 15 * SIZE) * (int)sizeof(float);          // 73728
    const int smem_s3 = (6 * SIZE * CBW + 2 * SIZE * EW) * (int)sizeof(float);  // 90112
    const int smem_b  = (UROWS * SIZE + RSTRIP * CW) * (int)sizeof(float);      // 39936

    cudaFuncSetAttribute(setup_ops_kernel, cudaFuncAttributeMaxDynamicSharedMemorySize, smem_so);
    cudaFuncSetAttribute(setup3_kernel,    cudaFuncAttributeMaxDynamicSharedMemorySize, smem_s3);
    cudaFuncSetAttribute(band_kernel,      cudaFuncAttributeMaxDynamicSharedMemorySize, smem_b);

    const int batch = out_size / (SIZE * SIZE);   // 2048

    setup_ops_kernel<<<6, 128, smem_so>>>(abx, atx, aqx, bby, bty, bqy);
    setup3_kernel<<<1, 1024, smem_s3>>>();
    band_kernel<<<batch * 2, 256, smem_b>>>(u, out);
}